// round 9
// baseline (speedup 1.0000x reference)
#include <cuda_runtime.h>
#include <cuda_fp16.h>
#include <cstdint>

// LUTBlock: out[b,o] = sum_{t=0..15} table[t, idx[b,t], o]
// idx[b,t] = sum_c ((x[b, aa[t,c]] - x[b, ab[t,c]]) > 0) << c
//
// R9: load-all-then-reduce with a 42-reg budget (occ 6) -> all 16 table LDGs
// in flight (MLP ~14 vs ~6), shrinking L2-hit-latency exposure. Keeps R8's
// pairwise HADD2 reduction, ballot-packed indices, fp16 table scratch.

#define B_SZ    16384
#define IN_F    1024
#define OUT_F   1024
#define T_CNT   16
#define C_CNT   8
#define R_CNT   256

#define TABLE_ELEMS (T_CNT * R_CNT * OUT_F)   // 4M elements

// 8 MB fp16 scratch copy of the table (device global: allocation-free).
__device__ __half g_table_h[TABLE_ELEMS];

// ---------------------------------------------------------------------------
// Pre-pass: fp32 table -> fp16 scratch. Each thread: 8 elems (32B in, 16B out).
// ---------------------------------------------------------------------------
__global__ __launch_bounds__(256)
void convert_table_kernel(const float4* __restrict__ table4)
{
    const int i = blockIdx.x * blockDim.x + threadIdx.x;   // 0 .. 512K-1
    const float4 v0 = __ldg(&table4[2 * i + 0]);
    const float4 v1 = __ldg(&table4[2 * i + 1]);
    half2 h[4];
    h[0] = __floats2half2_rn(v0.x, v0.y);
    h[1] = __floats2half2_rn(v0.z, v0.w);
    h[2] = __floats2half2_rn(v1.x, v1.y);
    h[3] = __floats2half2_rn(v1.z, v1.w);
    reinterpret_cast<uint4*>(g_table_h)[i] = *reinterpret_cast<const uint4*>(h);
}

// ---------------------------------------------------------------------------
// Main: one CTA per batch, 256 threads, occ 6 (regs ~42).
//   Phase 0: coalesced stage of x row (4KB) into smem.
//   Phase 1: 128 threads, one comparison each; ballot word = 4 packed index
//            bytes -> one STS.32 per warp; broadcast LDS.128 to hoist.
//   Phase 2: ALL 16 LDG.64 issued up front (front-batched, high MLP), then
//            pairwise HADD2 + fp32 accumulate. One STG.128.
// ---------------------------------------------------------------------------
__global__ __launch_bounds__(256, 6)
void lut_gather_sum_kernel(const float4* __restrict__ x4,
                           const int* __restrict__ aa,
                           const int* __restrict__ ab,
                           float4* __restrict__ out4)
{
    __shared__ float s_x[IN_F];
    __shared__ __align__(16) unsigned s_pk[4];

    const int tid = threadIdx.x;
    const int b   = blockIdx.x;

    // Phase 0: stage x row (256 x float4 = 4KB, fully coalesced).
    reinterpret_cast<float4*>(s_x)[tid] = __ldg(&x4[(size_t)b * (IN_F / 4) + tid]);
    __syncthreads();

    // Phase 1: threads 0..127 each do one comparison (t = tid>>3, c = tid&7).
    // Warp w's ballot bits [8k+c] correspond to (t = 4w+k, c): the 32-bit
    // ballot word is exactly the 4 packed index bytes for t = 4w..4w+3.
    if (tid < 128) {
        const int lane = tid & 31;
        const int ia = __ldg(&aa[tid]);
        const int ib = __ldg(&ab[tid]);
        const float d = s_x[ia] - s_x[ib];
        const unsigned m = __ballot_sync(0xFFFFFFFFu, d > 0.0f);
        if (lane == 0) s_pk[tid >> 5] = m;
    }
    __syncthreads();

    // Phase 2: gather-sum from fp16 table (L2-resident).
    const uint4 pk = *reinterpret_cast<const uint4*>(s_pk);  // 16 index bytes
    const char* base = reinterpret_cast<const char*>(g_table_h) + tid * 8;

    // Issue ALL 16 loads first: independent, front-batched by ptxas.
    uint2 v[T_CNT];
#pragma unroll
    for (int t = 0; t < T_CNT; t++) {
        const unsigned wd = (t < 4) ? pk.x : (t < 8) ? pk.y : (t < 12) ? pk.z : pk.w;
        const unsigned r = __byte_perm(wd, 0u, 0x4440 + (t & 3));   // index byte
        // byte offset: t * (256 rows * 2048 B) + r * 2048 ; t-part folds into
        // the LDG immediate.
        v[t] = __ldg(reinterpret_cast<const uint2*>(
                         base + (size_t)t * 524288u + r * 2048u));
    }

    // Reduce: pairwise fp16 pre-sum, then fp32 accumulate.
    float4 acc = make_float4(0.f, 0.f, 0.f, 0.f);
#pragma unroll
    for (int tp = 0; tp < T_CNT / 2; tp++) {
        const uint2 v0 = v[2 * tp];
        const uint2 v1 = v[2 * tp + 1];
        const half2 s0 = __hadd2(*reinterpret_cast<const half2*>(&v0.x),
                                 *reinterpret_cast<const half2*>(&v1.x));
        const half2 s1 = __hadd2(*reinterpret_cast<const half2*>(&v0.y),
                                 *reinterpret_cast<const half2*>(&v1.y));
        const float2 f0 = __half22float2(s0);
        const float2 f1 = __half22float2(s1);
        acc.x += f0.x;
        acc.y += f0.y;
        acc.z += f1.x;
        acc.w += f1.y;
    }

    out4[(size_t)b * (OUT_F / 4) + tid] = acc;
}

extern "C" void kernel_launch(void* const* d_in, const int* in_sizes, int n_in,
                              void* d_out, int out_size)
{
    const float4* x4     = (const float4*)d_in[0];  // (B, IN_F) fp32
    const float4* table4 = (const float4*)d_in[1];  // (T, R, OUT_F) fp32
    const int*    aa     = (const int*)   d_in[2];  // (T, C) int32
    const int*    ab     = (const int*)   d_in[3];  // (T, C) int32
    float4*       out4   = (float4*)      d_out;    // (B, OUT_F) fp32

    (void)in_sizes; (void)n_in; (void)out_size;

    // Pre-pass: table -> fp16 scratch (8 elems per thread)
    convert_table_kernel<<<TABLE_ELEMS / 8 / 256, 256>>>(table4);

    // Main gather-sum, 1 batch per CTA
    lut_gather_sum_kernel<<<B_SZ, 256>>>(x4, aa, ab, out4);
}

// round 10
// speedup vs baseline: 1.0391x; 1.0391x over previous
#include <cuda_runtime.h>
#include <cuda_fp16.h>
#include <cstdint>

// LUTBlock: out[b,o] = sum_{t=0..15} table[t, idx[b,t], o]
// idx[b,t] = sum_c ((x[b, aa[t,c]] - x[b, ab[t,c]]) > 0) << c
//
// R10: occ 8 restored; phase 2 = two front-batched waves of 8 LDG.64
// (MLP~8 within 32 regs) + depth-2 fp16 tree reduction (pairs->quads in
// HADD2, convert quad partials only). Ballot-packed indices, fp16 scratch.

#define B_SZ    16384
#define IN_F    1024
#define OUT_F   1024
#define T_CNT   16
#define C_CNT   8
#define R_CNT   256

#define TABLE_ELEMS (T_CNT * R_CNT * OUT_F)   // 4M elements

// 8 MB fp16 scratch copy of the table (device global: allocation-free).
__device__ __half g_table_h[TABLE_ELEMS];

// ---------------------------------------------------------------------------
// Pre-pass: fp32 table -> fp16 scratch. Each thread: 8 elems (32B in, 16B out).
// ---------------------------------------------------------------------------
__global__ __launch_bounds__(256)
void convert_table_kernel(const float4* __restrict__ table4)
{
    const int i = blockIdx.x * blockDim.x + threadIdx.x;   // 0 .. 512K-1
    const float4 v0 = __ldg(&table4[2 * i + 0]);
    const float4 v1 = __ldg(&table4[2 * i + 1]);
    half2 h[4];
    h[0] = __floats2half2_rn(v0.x, v0.y);
    h[1] = __floats2half2_rn(v0.z, v0.w);
    h[2] = __floats2half2_rn(v1.x, v1.y);
    h[3] = __floats2half2_rn(v1.z, v1.w);
    reinterpret_cast<uint4*>(g_table_h)[i] = *reinterpret_cast<const uint4*>(h);
}

// ---------------------------------------------------------------------------
// Reduce 8 table values (uint2 of 4 halves) with a depth-2 fp16 tree,
// accumulating the two quad partials into fp32 acc.
// ---------------------------------------------------------------------------
__device__ __forceinline__ void reduce8(const uint2* __restrict__ v, float4& acc)
{
#define H2(u) (*reinterpret_cast<const half2*>(&(u)))
    // slot x (output lanes 0,1)
    half2 p0 = __hadd2(H2(v[0].x), H2(v[1].x));
    half2 p1 = __hadd2(H2(v[2].x), H2(v[3].x));
    half2 p2 = __hadd2(H2(v[4].x), H2(v[5].x));
    half2 p3 = __hadd2(H2(v[6].x), H2(v[7].x));
    half2 qx0 = __hadd2(p0, p1);
    half2 qx1 = __hadd2(p2, p3);
    // slot y (output lanes 2,3)
    half2 r0 = __hadd2(H2(v[0].y), H2(v[1].y));
    half2 r1 = __hadd2(H2(v[2].y), H2(v[3].y));
    half2 r2 = __hadd2(H2(v[4].y), H2(v[5].y));
    half2 r3 = __hadd2(H2(v[6].y), H2(v[7].y));
    half2 qy0 = __hadd2(r0, r1);
    half2 qy1 = __hadd2(r2, r3);
#undef H2
    const float2 fx0 = __half22float2(qx0);
    const float2 fx1 = __half22float2(qx1);
    const float2 fy0 = __half22float2(qy0);
    const float2 fy1 = __half22float2(qy1);
    acc.x += fx0.x + fx1.x;
    acc.y += fx0.y + fx1.y;
    acc.z += fy0.x + fy1.x;
    acc.w += fy0.y + fy1.y;
}

// ---------------------------------------------------------------------------
// Main: one CTA per batch, 256 threads, occ 8 (<=32 regs).
// ---------------------------------------------------------------------------
__global__ __launch_bounds__(256, 8)
void lut_gather_sum_kernel(const float4* __restrict__ x4,
                           const int* __restrict__ aa,
                           const int* __restrict__ ab,
                           float4* __restrict__ out4)
{
    __shared__ float s_x[IN_F];
    __shared__ __align__(16) unsigned s_pk[4];

    const int tid = threadIdx.x;
    const int b   = blockIdx.x;

    // Phase 0: stage x row (256 x float4 = 4KB, fully coalesced).
    reinterpret_cast<float4*>(s_x)[tid] = __ldg(&x4[(size_t)b * (IN_F / 4) + tid]);
    __syncthreads();

    // Phase 1: threads 0..127 each do one comparison (t = tid>>3, c = tid&7).
    // Warp w's ballot word is exactly the 4 packed index bytes for t=4w..4w+3.
    if (tid < 128) {
        const int lane = tid & 31;
        const int ia = __ldg(&aa[tid]);
        const int ib = __ldg(&ab[tid]);
        const float d = s_x[ia] - s_x[ib];
        const unsigned m = __ballot_sync(0xFFFFFFFFu, d > 0.0f);
        if (lane == 0) s_pk[tid >> 5] = m;
    }
    __syncthreads();

    // Phase 2: gather-sum from fp16 table (L2-resident), two 8-load waves.
    const uint4 pk = *reinterpret_cast<const uint4*>(s_pk);  // 16 index bytes
    const char* base = reinterpret_cast<const char*>(g_table_h) + tid * 8;

    float4 acc = make_float4(0.f, 0.f, 0.f, 0.f);

    {   // wave A: t = 0..7 (index bytes in pk.x, pk.y)
        uint2 v[8];
#pragma unroll
        for (int t = 0; t < 8; t++) {
            const unsigned wd = (t < 4) ? pk.x : pk.y;
            const unsigned r = __byte_perm(wd, 0u, 0x4440 + (t & 3));
            v[t] = __ldg(reinterpret_cast<const uint2*>(
                             base + (size_t)t * 524288u + r * 2048u));
        }
        reduce8(v, acc);
    }
    {   // wave B: t = 8..15 (index bytes in pk.z, pk.w)
        uint2 v[8];
#pragma unroll
        for (int t = 0; t < 8; t++) {
            const unsigned wd = (t < 4) ? pk.z : pk.w;
            const unsigned r = __byte_perm(wd, 0u, 0x4440 + (t & 3));
            v[t] = __ldg(reinterpret_cast<const uint2*>(
                             base + (size_t)(t + 8) * 524288u + r * 2048u));
        }
        reduce8(v, acc);
    }

    out4[(size_t)b * (OUT_F / 4) + tid] = acc;
}

extern "C" void kernel_launch(void* const* d_in, const int* in_sizes, int n_in,
                              void* d_out, int out_size)
{
    const float4* x4     = (const float4*)d_in[0];  // (B, IN_F) fp32
    const float4* table4 = (const float4*)d_in[1];  // (T, R, OUT_F) fp32
    const int*    aa     = (const int*)   d_in[2];  // (T, C) int32
    const int*    ab     = (const int*)   d_in[3];  // (T, C) int32
    float4*       out4   = (float4*)      d_out;    // (B, OUT_F) fp32

    (void)in_sizes; (void)n_in; (void)out_size;

    // Pre-pass: table -> fp16 scratch (8 elems per thread)
    convert_table_kernel<<<TABLE_ELEMS / 8 / 256, 256>>>(table4);

    // Main gather-sum, 1 batch per CTA
    lut_gather_sum_kernel<<<B_SZ, 256>>>(x4, aa, ab, out4);
}